// round 7
// baseline (speedup 1.0000x reference)
#include <cuda_runtime.h>

#define B_TOTAL 32768
#define NNODES  16
#define NDIM    64
#define HID     128
#define NC      10
#define G       4
#define THREADS 256
#define HPAD    132                 // hg row stride
#define QPAD    144                 // q/k/v row stride; head h at offset 36h

// shared memory layout (float offsets)
#define OFF_WB0   0                 // 8192 fl = 32KB weight chunk buffer 0
#define OFF_WB1   8192              // buffer 1
#define OFF_BIAS  16384
#define   B_ENC   0
#define   B_BQ    128               // +128*l
#define   B_BK    384
#define   B_BV    640
#define   B_LNG   896
#define   B_LNB   1152
#define   B_B1    1408
#define   B_B2    1536
#define OFF_MBAR  17984             // 2 mbarriers (16 B), 16B-aligned
#define OFF_DATA  18048
#define GFL       (16*HPAD + 3*16*QPAD)     // 2112 + 6912 = 9024 per graph
#define SMEM_FLOATS (OFF_DATA + G*GFL)      // 54144
#define SMEM_BYTES  (SMEM_FLOATS*4)         // 216576
#define MBAR_B    (OFF_MBAR*4)

typedef unsigned long long ull;

__device__ __forceinline__ ull pack2(float x, float y) {
    ull r; asm("mov.b64 %0, {%1,%2};" : "=l"(r) : "f"(x), "f"(y)); return r;
}
__device__ __forceinline__ float2 unpack2(ull v) {
    float2 r; asm("mov.b64 {%0,%1}, %2;" : "=f"(r.x), "=f"(r.y) : "l"(v)); return r;
}
__device__ __forceinline__ void fma2(ull& d, ull a, ull b) {
    asm("fma.rn.f32x2 %0, %1, %2, %0;" : "+l"(d) : "l"(a), "l"(b));
}
__device__ __forceinline__ unsigned su32(const void* p) {
    return (unsigned)__cvta_generic_to_shared(p);
}
__device__ __forceinline__ void mbar_init(unsigned a, unsigned cnt) {
    asm volatile("mbarrier.init.shared.b64 [%0], %1;" :: "r"(a), "r"(cnt) : "memory");
}
__device__ __forceinline__ void mbw(unsigned a, unsigned parity) {
    asm volatile("{\n\t.reg .pred P;\nWAIT%=:\n\t"
        "mbarrier.try_wait.parity.acquire.cta.shared::cta.b64 P, [%0], %1, 0x989680;\n\t"
        "@!P bra WAIT%=;\n\t}" :: "r"(a), "r"(parity) : "memory");
}
__device__ __forceinline__ void bulk_issue(unsigned dst, const float* src,
                                           unsigned bytes, unsigned mbar) {
    asm volatile("mbarrier.arrive.expect_tx.shared::cta.b64 _, [%0], %1;"
                 :: "r"(mbar), "r"(bytes) : "memory");
    asm volatile("cp.async.bulk.shared::cluster.global.mbarrier::complete_tx::bytes "
                 "[%0], [%1], %2, [%3];"
                 :: "r"(dst), "l"(src), "r"(bytes), "r"(mbar) : "memory");
}

// R4 column-paired gemm over a 64-row weight chunk.
// Lane owns 4 contiguous output cols c..c+3; accA=(c,c+1), accB=(c+2,c+3).
// W packs are register-consecutive (free); h dup-packs lower to fma-pipe MOVs.
template<int INSTRIDE>
__device__ __forceinline__ void gemm64(const float* __restrict__ in,
                                       const float* __restrict__ Wc,
                                       int c, ull* accA, ull* accB)
{
#pragma unroll 2
    for (int k0 = 0; k0 < 64; k0 += 4) {
        float4 w0 = *(const float4*)(Wc + (k0    )*HID + c);
        float4 w1 = *(const float4*)(Wc + (k0 + 1)*HID + c);
        float4 w2 = *(const float4*)(Wc + (k0 + 2)*HID + c);
        float4 w3 = *(const float4*)(Wc + (k0 + 3)*HID + c);
        ull w0A = pack2(w0.x, w0.y), w0B = pack2(w0.z, w0.w);
        ull w1A = pack2(w1.x, w1.y), w1B = pack2(w1.z, w1.w);
        ull w2A = pack2(w2.x, w2.y), w2B = pack2(w2.z, w2.w);
        ull w3A = pack2(w3.x, w3.y), w3B = pack2(w3.z, w3.w);
#pragma unroll
        for (int n = 0; n < 8; n++) {
            float4 hv = *(const float4*)(in + n*INSTRIDE + k0);
            ull h0 = pack2(hv.x, hv.x), h1 = pack2(hv.y, hv.y);
            ull h2 = pack2(hv.z, hv.z), h3 = pack2(hv.w, hv.w);
            fma2(accA[n], h0, w0A); fma2(accB[n], h0, w0B);
            fma2(accA[n], h1, w1A); fma2(accB[n], h1, w1B);
            fma2(accA[n], h2, w2A); fma2(accB[n], h2, w2B);
            fma2(accA[n], h3, w3A); fma2(accB[n], h3, w3B);
        }
    }
}

__device__ __forceinline__ void acc_init(ull* accA, ull* accB,
                                         const float* __restrict__ bp, int c) {
    ull bA = pack2(bp[c],     bp[c + 1]);
    ull bB = pack2(bp[c + 2], bp[c + 3]);
#pragma unroll
    for (int n = 0; n < 8; n++) { accA[n] = bA; accB[n] = bB; }
}

template<int OPAD>
__device__ __forceinline__ void store_acc(float* __restrict__ out, int n0, int off,
                                          const ull* accA, const ull* accB)
{
#pragma unroll
    for (int n = 0; n < 8; n++) {
        float2 a = unpack2(accA[n]), b = unpack2(accB[n]);
        *(float4*)(out + (n0 + n)*OPAD + off) = make_float4(a.x, a.y, b.x, b.y);
    }
}

__global__ void __launch_bounds__(THREADS, 1)
gnn_fused_kernel(const float* __restrict__ x,
                 const float* __restrict__ enc_W, const float* __restrict__ enc_b,
                 const float* __restrict__ Wq, const float* __restrict__ bq,
                 const float* __restrict__ Wk, const float* __restrict__ bk,
                 const float* __restrict__ Wv, const float* __restrict__ bv,
                 const float* __restrict__ ln_g, const float* __restrict__ ln_b,
                 const float* __restrict__ W1, const float* __restrict__ b1,
                 const float* __restrict__ W2, const float* __restrict__ b2,
                 float* __restrict__ out)
{
    extern __shared__ float sm[];
    const unsigned smb = su32(sm);
    float* bias = sm + OFF_BIAS;

    const int tid  = threadIdx.x;
    const int lane = tid & 31;
    const int warp = tid >> 5;
    const int gs   = warp >> 1;
    const int wsub = warp & 1;
    const int n0   = wsub * 8;
    const int c    = lane << 2;                       // my 4 output columns
    const int qoff = (c >> 5)*36 + (c & 31);          // head-padded offset

    float* hg = sm + OFF_DATA + gs*GFL;
    float* qg = hg + 16*HPAD;          // +2112
    float* kg = qg + 16*QPAD;          // +2304
    float* vg = kg + 16*QPAD;

    // ---- mbarriers + first two weight chunks ----
    if (tid == 0) {
        mbar_init(smb + MBAR_B,     1);
        mbar_init(smb + MBAR_B + 8, 1);
        asm volatile("fence.proxy.async.shared::cta;" ::: "memory");
        bulk_issue(smb + OFF_WB0*4, enc_W, 32768u, smb + MBAR_B);       // c0
        bulk_issue(smb + OFF_WB1*4, Wq,    32768u, smb + MBAR_B + 8);   // c1
    }

    // ---- preload biases / ln params ----
    for (int i = tid; i < 128; i += THREADS) {
        bias[B_ENC + i] = enc_b[i];
        bias[B_B1  + i] = b1[i];
    }
    for (int i = tid; i < 256; i += THREADS) {
        bias[B_BQ  + i] = bq[i];
        bias[B_BK  + i] = bk[i];
        bias[B_BV  + i] = bv[i];
        bias[B_LNG + i] = ln_g[i];
        bias[B_LNB + i] = ln_b[i];
    }
    if (tid < NC) bias[B_B2 + tid] = b2[tid];

    // ---- stage x (4 graphs x 1024 floats) into Q region, row stride 64 ----
    {
        const float4* xs = (const float4*)(x + (size_t)blockIdx.x * (G*NNODES*NDIM));
        float* xb = sm + OFF_DATA + 16*HPAD;     // qg of graph 0
        for (int i = tid; i < (G*NNODES*NDIM)/4; i += THREADS) {
            int g = i >> 8;              // 256 float4 per graph
            int r = i & 255;
            *(float4*)(xb + g*GFL + (r << 2)) = xs[i];
        }
    }
    __syncthreads();    // publish biases + x staging + mbarrier init

    int wc = 0;         // next chunk to consume
    int ic = 2;         // next chunk to issue
#define TWAIT() mbw(smb + MBAR_B + (wc & 1)*8, (wc >> 1) & 1)
#define TISSUE(src, bytes) do { if (tid == 0) \
        bulk_issue(smb + ((ic & 1) ? OFF_WB1 : OFF_WB0)*4, (src), (bytes), \
                   smb + MBAR_B + (ic & 1)*8); ic++; } while (0)

    ull accA[8], accB[8];

    // ---- encode: h = x @ enc_W + enc_b  (K=64, one chunk) ----
    {
        TWAIT();                               // c0
        acc_init(accA, accB, bias + B_ENC, c);
        gemm64<NDIM>(qg + n0*NDIM, sm + OFF_WB0, c, accA, accB);
        store_acc<HPAD>(hg, n0, c, accA, accB);
        __syncthreads();
        TISSUE(Wq + 8192, 32768u);             // c2: Wq[0] rows 64..127
        wc = 1;
    }

    const float scale = 0.1767766952966369f;   // 1/sqrt(32)

    for (int l = 0; l < 2; l++) {
        const float* nexts[6] = {
            Wk + l*16384, Wk + l*16384 + 8192,
            Wv + l*16384, Wv + l*16384 + 8192,
            (l == 0) ? (Wq + 16384) : W1,
            (l == 0) ? (Wq + 16384 + 8192) : (W1 + 8192)
        };
        const float* bptr[3] = { bias + B_BQ + 128*l, bias + B_BK + 128*l,
                                 bias + B_BV + 128*l };
        float* outs[3] = { qg, kg, vg };

#pragma unroll
        for (int s = 0; s < 3; s++) {
            TWAIT();
            acc_init(accA, accB, bptr[s], c);
            gemm64<HPAD>(hg + n0*HPAD, sm + ((wc & 1) ? OFF_WB1 : OFF_WB0), c, accA, accB);
            __syncthreads();
            TISSUE(nexts[2*s], 32768u);
            wc++;
            TWAIT();
            gemm64<HPAD>(hg + n0*HPAD + 64, sm + ((wc & 1) ? OFF_WB1 : OFF_WB0), c, accA, accB);
            store_acc<QPAD>(outs[s], n0, qoff, accA, accB);
            __syncthreads();
            TISSUE(nexts[2*s + 1], 32768u);
            wc++;
        }

        // ---- attention + residual + layernorm (registers; lane=(node,head)) ----
        {
            const int n  = n0 + (lane & 7);
            const int hh = lane >> 3;
            const int co = hh * 36;      // q/k/v head-padded offset
            const int ch = hh * 32;      // hg linear offset

            float q[32];
            const float* qr = qg + n*QPAD + co;
#pragma unroll
            for (int j = 0; j < 8; j++) {
                float4 t = *(const float4*)(qr + 4*j);
                q[4*j] = t.x; q[4*j+1] = t.y; q[4*j+2] = t.z; q[4*j+3] = t.w;
            }
            float s[16];
#pragma unroll
            for (int m = 0; m < 16; m++) {
                const float* kr = kg + m*QPAD + co;
                float a0 = 0.f, a1 = 0.f, a2 = 0.f, a3 = 0.f;
#pragma unroll
                for (int j = 0; j < 8; j++) {
                    float4 t = *(const float4*)(kr + 4*j);
                    a0 += q[4*j]  *t.x; a1 += q[4*j+1]*t.y;
                    a2 += q[4*j+2]*t.z; a3 += q[4*j+3]*t.w;
                }
                s[m] = (a0 + a1 + a2 + a3) * scale;
            }
            float mx = s[0];
#pragma unroll
            for (int m = 1; m < 16; m++) mx = fmaxf(mx, s[m]);
            float ssum = 0.f;
#pragma unroll
            for (int m = 0; m < 16; m++) { s[m] = __expf(s[m] - mx); ssum += s[m]; }
            float inv = 1.f / ssum;

            float o[32];
#pragma unroll
            for (int j = 0; j < 32; j++) o[j] = 0.f;
#pragma unroll
            for (int m = 0; m < 16; m++) {
                float p = s[m] * inv;
                const float* vr = vg + m*QPAD + co;
#pragma unroll
                for (int j = 0; j < 8; j++) {
                    float4 t = *(const float4*)(vr + 4*j);
                    o[4*j]   += p*t.x; o[4*j+1] += p*t.y;
                    o[4*j+2] += p*t.z; o[4*j+3] += p*t.w;
                }
            }
            // residual
            float* hr = hg + n*HPAD + ch;
#pragma unroll
            for (int j = 0; j < 8; j++) {
                float4 t = *(const float4*)(hr + 4*j);
                o[4*j] += t.x; o[4*j+1] += t.y; o[4*j+2] += t.z; o[4*j+3] += t.w;
            }
            // LN stats across the 4 head-lanes of this node
            float lsum = 0.f, lsq = 0.f;
#pragma unroll
            for (int j = 0; j < 32; j++) { lsum += o[j]; lsq += o[j]*o[j]; }
            lsum += __shfl_xor_sync(0xffffffffu, lsum, 8);
            lsq  += __shfl_xor_sync(0xffffffffu, lsq,  8);
            lsum += __shfl_xor_sync(0xffffffffu, lsum, 16);
            lsq  += __shfl_xor_sync(0xffffffffu, lsq,  16);
            float mean = lsum * (1.f/HID);
            float var  = lsq  * (1.f/HID) - mean*mean;
            float rstd = rsqrtf(var + 1e-5f);
#pragma unroll
            for (int j = 0; j < 32; j++)
                o[j] = (o[j] - mean) * rstd * bias[B_LNG + 128*l + ch + j]
                       + bias[B_LNB + 128*l + ch + j];
#pragma unroll
            for (int j = 0; j < 8; j++)
                *(float4*)(hr + 4*j) = make_float4(o[4*j], o[4*j+1], o[4*j+2], o[4*j+3]);
        }
        __syncthreads();
    }

    // ---- pooling into qg scratch: [0..128)=mean, [128..256)=max ----
    {
        int cA = wsub*64 + lane, cB = cA + 32;
        float sA = 0.f, sB = 0.f, mA = -3.4e38f, mB = -3.4e38f;
#pragma unroll
        for (int nn = 0; nn < 16; nn++) {
            float a = hg[nn*HPAD + cA]; sA += a; mA = fmaxf(mA, a);
            float b = hg[nn*HPAD + cB]; sB += b; mB = fmaxf(mB, b);
        }
        qg[cA]       = sA * (1.f/16.f);
        qg[HID + cA] = mA;
        qg[cB]       = sB * (1.f/16.f);
        qg[HID + cB] = mB;
    }
    __syncthreads();

    // ---- MLP layer 1: 4 chunks of W1 (256x128); c13,c14 already in flight ----
    {
        int cA = wsub*64 + lane, cB = cA + 32;
        float a1 = bias[B_B1 + cA];
        float a2 = bias[B_B1 + cB];
        for (int cc = 0; cc < 4; cc++) {
            TWAIT();
            float* bufp = sm + ((wc & 1) ? OFF_WB1 : OFF_WB0);
#pragma unroll 8
            for (int k = 0; k < 64; k++) {
                float pv = qg[64*cc + k];
                a1 = fmaf(pv, bufp[k*HID + cA], a1);
                a2 = fmaf(pv, bufp[k*HID + cB], a2);
            }
            __syncthreads();
            if (cc < 3) {
                const float* src = (cc < 2) ? (W1 + (cc + 2)*8192) : W2;
                unsigned nb = (cc < 2) ? 32768u : 5120u;   // W2 = 128*10 fl = 5120 B
                TISSUE(src, nb);
            }
            wc++;
        }
        kg[cA] = fmaxf(a1, 0.f);
        kg[cB] = fmaxf(a2, 0.f);
    }
    __syncthreads();

    // ---- logits = hid @ W2 + b2 ----
    TWAIT();    // c17
    {
        const float* Wc = sm + ((wc & 1) ? OFF_WB1 : OFF_WB0);
        if (wsub == 0 && lane < NC) {
            float a = bias[B_B2 + lane];
#pragma unroll 8
            for (int k = 0; k < HID; k++)
                a = fmaf(kg[k], Wc[k*NC + lane], a);
            out[((size_t)blockIdx.x*G + gs)*NC + lane] = a;
        }
    }
#undef TWAIT
#undef TISSUE
}

extern "C" void kernel_launch(void* const* d_in, const int* in_sizes, int n_in,
                              void* d_out, int out_size)
{
    const float* x     = (const float*)d_in[0];
    const float* enc_W = (const float*)d_in[1];
    const float* enc_b = (const float*)d_in[2];
    const float* Wq    = (const float*)d_in[3];
    const float* bq    = (const float*)d_in[4];
    const float* Wk    = (const float*)d_in[5];
    const float* bk    = (const float*)d_in[6];
    const float* Wv    = (const float*)d_in[7];
    const float* bv    = (const float*)d_in[8];
    const float* ln_g  = (const float*)d_in[9];
    const float* ln_b  = (const float*)d_in[10];
    const float* W1    = (const float*)d_in[11];
    const float* b1    = (const float*)d_in[12];
    const float* W2    = (const float*)d_in[13];
    const float* b2    = (const float*)d_in[14];
    float* out = (float*)d_out;

    cudaFuncSetAttribute(gnn_fused_kernel,
                         cudaFuncAttributeMaxDynamicSharedMemorySize, SMEM_BYTES);

    gnn_fused_kernel<<<B_TOTAL / G, THREADS, SMEM_BYTES>>>(
        x, enc_W, enc_b, Wq, bq, Wk, bk, Wv, bv, ln_g, ln_b, W1, b1, W2, b2, out);
}

// round 9
// speedup vs baseline: 1.6913x; 1.6913x over previous
#include <cuda_runtime.h>
#include <cuda_bf16.h>

#define B_TOTAL 32768
#define HID 128
#define NC  10
#define G   4
#define THREADS 256
#define HPAD 132
#define QPAD 144
#define XPAD 68

#define OFF_BIAS 17408          // B-tile region = floats [0,17408) = 69632 B
#define   B_ENC 0
#define   B_BQ  128
#define   B_BK  384
#define   B_BV  640
#define   B_LNG 896
#define   B_LNB 1152
#define   B_B1  1408
#define   B_B2  1536
#define OFF_DATA 19072
#define GFL (16*HPAD + 3*16*QPAD)           // 9024
#define SMEM_FLOATS (OFF_DATA + G*GFL)      // 55168
#define SMEM_BYTES  (SMEM_FLOATS*4)         // 220672
#define MB0 ((OFF_BIAS + 1600)*4)
#define MB1 (MB0 + 8)

#define BROW 136                 // bf16 elements per padded B row
#define BVER 34816               // bytes per version (128 rows * 272 B)
#define BPROJ 69632              // hi + lo

__device__ __align__(16) unsigned char g_wpre[7*BPROJ];

static __device__ __forceinline__ unsigned su32(const void* p) {
    return (unsigned)__cvta_generic_to_shared(p);
}
static __device__ __forceinline__ void mbar_init(unsigned a, unsigned c) {
    asm volatile("mbarrier.init.shared.b64 [%0], %1;" :: "r"(a), "r"(c) : "memory");
}
static __device__ __forceinline__ void mbw(unsigned a, unsigned par) {
    asm volatile("{\n\t.reg .pred P;\nW%=:\n\t"
        "mbarrier.try_wait.parity.acquire.cta.shared::cta.b64 P, [%0], %1, 0x989680;\n\t"
        "@!P bra W%=;\n\t}" :: "r"(a), "r"(par) : "memory");
}
static __device__ __forceinline__ void bulk_issue(unsigned dst, const void* src,
                                                  unsigned bytes, unsigned mbar) {
    asm volatile("mbarrier.arrive.expect_tx.shared::cta.b64 _, [%0], %1;"
                 :: "r"(mbar), "r"(bytes) : "memory");
    asm volatile("cp.async.bulk.shared::cluster.global.mbarrier::complete_tx::bytes "
                 "[%0], [%1], %2, [%3];" :: "r"(dst), "l"(src), "r"(bytes), "r"(mbar)
                 : "memory");
}

#define LDSM4(r0,r1,r2,r3,adr) asm volatile( \
    "ldmatrix.sync.aligned.m8n8.x4.shared.b16 {%0,%1,%2,%3}, [%4];" \
    : "=r"(r0), "=r"(r1), "=r"(r2), "=r"(r3) : "r"(adr))

#define MMA4(acp,a,b0,b1) asm volatile( \
    "mma.sync.aligned.m16n8k16.row.col.f32.bf16.bf16.f32 " \
    "{%0,%1,%2,%3}, {%4,%5,%6,%7}, {%8,%9}, {%0,%1,%2,%3};" \
    : "+f"((acp)[0]), "+f"((acp)[1]), "+f"((acp)[2]), "+f"((acp)[3]) \
    : "r"((a)[0]), "r"((a)[1]), "r"((a)[2]), "r"((a)[3]), "r"(b0), "r"(b1))

// fp32 pair -> bf16x2 hi (lo lane = first elem) + bf16x2 residual
static __device__ __forceinline__ void split2(float2 f, unsigned& hi, unsigned& lo) {
    asm("cvt.rn.bf16x2.f32 %0, %1, %2;" : "=r"(hi) : "f"(f.y), "f"(f.x));
    float lx = f.x - __uint_as_float(hi << 16);
    float ly = f.y - __uint_as_float(hi & 0xffff0000u);
    asm("cvt.rn.bf16x2.f32 %0, %1, %2;" : "=r"(lo) : "f"(ly), "f"(lx));
}

// ---------- prep: transposed bf16 hi/lo padded B images ----------
__global__ void prep_kernel(const float* __restrict__ encW, const float* __restrict__ Wq,
                            const float* __restrict__ Wk,  const float* __restrict__ Wv)
{
    int p = blockIdx.x;
    const float* src; int K;
    if (p == 0) { src = encW; K = 64; }
    else {
        int i = p - 1, l = i / 3, w = i % 3;
        src = (w == 0 ? Wq : w == 1 ? Wk : Wv) + l*16384; K = 128;
    }
    unsigned char* dhi = g_wpre + p*BPROJ;
    for (int idx = threadIdx.x; idx < 128*BROW; idx += blockDim.x) {
        int n = idx / BROW, kk = idx % BROW;
        float v = (kk < K) ? src[kk*128 + n] : 0.f;
        __nv_bfloat16 h = __float2bfloat16(v);
        __nv_bfloat16 lo = __float2bfloat16(v - __bfloat162float(h));
        *(__nv_bfloat16*)(dhi + n*(BROW*2) + kk*2)        = h;
        *(__nv_bfloat16*)(dhi + BVER + n*(BROW*2) + kk*2) = lo;
    }
}

// warp MMA for one projection half (N=64 cols), 3-pass bf16 split
template<int KSTEPS>
static __device__ __forceinline__ void mma_proj(const float* __restrict__ A, int astride,
                                                unsigned btHi, float* __restrict__ acc,
                                                int lane)
{
    const int g  = lane >> 2, q2 = (lane & 3) << 1;
    const int m  = lane >> 3, r  = lane & 7;
    const unsigned bthr = (unsigned)((((m >> 1)*8 + r)*BROW + (m & 1)*8)*2);
#pragma unroll
    for (int ks = 0; ks < KSTEPS; ks++) {
        const int kb = ks*16;
        float2 f0 = *(const float2*)(A + g*astride + kb + q2);
        float2 f1 = *(const float2*)(A + (g + 8)*astride + kb + q2);
        float2 f2 = *(const float2*)(A + g*astride + kb + 8 + q2);
        float2 f3 = *(const float2*)(A + (g + 8)*astride + kb + 8 + q2);
        unsigned ah[4], al[4];
        split2(f0, ah[0], al[0]); split2(f1, ah[1], al[1]);
        split2(f2, ah[2], al[2]); split2(f3, ah[3], al[3]);
#pragma unroll
        for (int j = 0; j < 4; j++) {
            unsigned adr = btHi + (unsigned)(j*(16*BROW*2) + kb*2) + bthr;
            unsigned bh0, bh1, bh2, bh3, bl0, bl1, bl2, bl3;
            LDSM4(bh0, bh1, bh2, bh3, adr);
            LDSM4(bl0, bl1, bl2, bl3, adr + BVER);
            float* aA = acc + (2*j)*4;
            float* aB = acc + (2*j + 1)*4;
            MMA4(aA, ah, bh0, bh1);  MMA4(aB, ah, bh2, bh3);
            MMA4(aA, al, bh0, bh1);  MMA4(aB, al, bh2, bh3);
            MMA4(aA, ah, bl0, bl1);  MMA4(aB, ah, bl2, bl3);
        }
    }
}

static __device__ __forceinline__ void acc_init(float* acc, const float* __restrict__ bp,
                                                int lane, int wsub) {
    const int q2 = (lane & 3) << 1;
#pragma unroll
    for (int nt = 0; nt < 8; nt++) {
        int lc = 64*wsub + nt*8 + q2;
        acc[nt*4]     = bp[lc];
        acc[nt*4 + 1] = bp[lc + 1];
        acc[nt*4 + 2] = bp[lc];
        acc[nt*4 + 3] = bp[lc + 1];
    }
}

template<int OPAD, bool HEADOFF>
static __device__ __forceinline__ void epi_store(float* __restrict__ ob,
                                                 const float* __restrict__ acc,
                                                 int lane, int wsub) {
    const int g = lane >> 2, q2 = (lane & 3) << 1;
#pragma unroll
    for (int nt = 0; nt < 8; nt++) {
        int lc  = 64*wsub + nt*8 + q2;
        int off = HEADOFF ? ((lc >> 5)*36 + (lc & 31)) : lc;
        *(float2*)(ob + g*OPAD + off)       = make_float2(acc[nt*4],     acc[nt*4 + 1]);
        *(float2*)(ob + (g + 8)*OPAD + off) = make_float2(acc[nt*4 + 2], acc[nt*4 + 3]);
    }
}

__global__ void __launch_bounds__(THREADS, 1)
gnn_mma_kernel(const float* __restrict__ x,
               const float* __restrict__ enc_b, const float* __restrict__ bq,
               const float* __restrict__ bk,    const float* __restrict__ bv,
               const float* __restrict__ ln_g,  const float* __restrict__ ln_b,
               const float* __restrict__ W1,    const float* __restrict__ b1,
               const float* __restrict__ W2,    const float* __restrict__ b2,
               float* __restrict__ out)
{
    extern __shared__ float sm[];
    const unsigned smb = su32(sm);
    float* bias = sm + OFF_BIAS;
    const int tid = threadIdx.x, lane = tid & 31, warp = tid >> 5;
    const int gs = warp >> 1, wsub = warp & 1, n0 = wsub * 8;

    if (tid == 0) {
        mbar_init(smb + MB0, 1); mbar_init(smb + MB1, 1);
        asm volatile("fence.proxy.async.shared::cta;" ::: "memory");
        bulk_issue(smb,        g_wpre,        BVER, smb + MB0);   // enc hi
        bulk_issue(smb + BVER, g_wpre + BVER, BVER, smb + MB1);   // enc lo
    }
    for (int i = tid; i < 128; i += THREADS) { bias[B_ENC+i] = enc_b[i]; bias[B_B1+i] = b1[i]; }
    for (int i = tid; i < 256; i += THREADS) {
        bias[B_BQ+i] = bq[i]; bias[B_BK+i] = bk[i]; bias[B_BV+i] = bv[i];
        bias[B_LNG+i] = ln_g[i]; bias[B_LNB+i] = ln_b[i];
    }
    if (tid < NC) bias[B_B2 + tid] = b2[tid];
    {   // stage x rows (stride XPAD) into q region
        const float4* xs = (const float4*)(x + (size_t)blockIdx.x * (G*16*64));
        float* xb = sm + OFF_DATA + 16*HPAD;
        for (int i = tid; i < (G*16*64)/4; i += THREADS) {
            int g = i >> 8, row = (i & 255) >> 4, w4 = (i & 15) << 2;
            *(float4*)(xb + g*GFL + row*XPAD + w4) = xs[i];
        }
    }
    __syncthreads();

    float* hg = sm + OFF_DATA + gs*GFL;
    float* qg = hg + 16*HPAD;
    float* kg = qg + 16*QPAD;
    float* vg = kg + 16*QPAD;
    const unsigned btW = smb + (unsigned)(wsub*64*BROW*2);   // warp's B half base

    float acc[32];

    // ---- encode: h = x @ enc_W + enc_b ----
    mbw(smb + MB0, 0); mbw(smb + MB1, 0);
    acc_init(acc, bias + B_ENC, lane, wsub);
    mma_proj<4>(qg, XPAD, btW, acc, lane);
    __syncthreads();
    if (tid == 0) {
        bulk_issue(smb,        g_wpre + BPROJ,        BVER, smb + MB0);
        bulk_issue(smb + BVER, g_wpre + BPROJ + BVER, BVER, smb + MB1);
    }
    epi_store<HPAD, false>(hg, acc, lane, wsub);
    __syncthreads();

    const float scale = 0.1767766952966369f;
    for (int l = 0; l < 2; l++) {
        for (int s = 0; s < 3; s++) {
            int pidx = 1 + l*3 + s;
            mbw(smb + MB0, pidx & 1); mbw(smb + MB1, pidx & 1);
            const float* bp = bias + (s == 0 ? B_BQ : s == 1 ? B_BK : B_BV) + 128*l;
            acc_init(acc, bp, lane, wsub);
            mma_proj<8>(hg, HPAD, btW, acc, lane);
            __syncthreads();
            if (tid == 0) {
                int np = pidx + 1;
                if (np <= 6) {
                    bulk_issue(smb,        g_wpre + np*BPROJ,        BVER, smb + MB0);
                    bulk_issue(smb + BVER, g_wpre + np*BPROJ + BVER, BVER, smb + MB1);
                } else {
                    bulk_issue(smb, W1, 65536u, smb + MB0);          // W1 rows 0..127
                }
            }
            float* dst = (s == 0 ? qg : s == 1 ? kg : vg);
            epi_store<QPAD, true>(dst, acc, lane, wsub);
        }
        __syncthreads();

        // ---- attention + residual + LN (R6, unchanged) ----
        {
            const int n  = n0 + (lane & 7);
            const int hh = lane >> 3;
            const int co = hh * 36, ch = hh * 32;
            float q[32];
            const float* qr = qg + n*QPAD + co;
#pragma unroll
            for (int j = 0; j < 8; j++) {
                float4 t = *(const float4*)(qr + 4*j);
                q[4*j] = t.x; q[4*j+1] = t.y; q[4*j+2] = t.z; q[4*j+3] = t.w;
            }
            float s[16];
#pragma unroll
            for (int m = 0; m < 16; m++) {
                const float* kr = kg + m*QPAD + co;
                float a0 = 0.f, a1 = 0.f, a2 = 0.f, a3 = 0.f;
#pragma unroll
                for (int j = 0; j < 8; j++) {
                    float4 t = *(const float4*)(kr + 4*j);
                    a0 += q[4*j]*t.x; a1 += q[4*j+1]*t.y;
                    a2 += q[4*j+2]*t.z; a3 += q[4*j+3]*t.w;
                }
                s[m] = (a0 + a1 + a2 + a3) * scale;
            }
            float mx = s[0];
#pragma unroll
            for (int m = 1; m < 16; m++) mx = fmaxf(mx, s[m]);
            float ssum = 0.f;
#pragma unroll
            for (int m = 0; m < 16; m++) { s[m] = __expf(s[m] - mx); ssum += s[m]; }
            float inv = 1.f / ssum;
            float o[32];
#pragma unroll
            for (int j = 0; j < 32; j++) o[j] = 0.f;
#pragma unroll
            for (int m = 0; m < 16; m++) {
                float p = s[m] * inv;
                const float* vr = vg + m*QPAD + co;
#pragma unroll
                for (int j = 0; j < 8; j++) {
                    float4 t = *(const float4*)(vr + 4*j);
                    o[4*j] += p*t.x; o[4*j+1] += p*t.y;
                    o[4*j+2] += p*t.z; o[4*j+3] += p*t.w;
                }
            }
            float* hr = hg + n*HPAD + ch;
#pragma unroll
            for (int j = 0; j < 8; j++) {
                float4 t = *(const float4*)(hr + 4*j);
                o[4*j] += t.x; o[4*j+1] += t.y; o[4*j+2] += t.z; o[4*j+3] += t.w;
            }
            float lsum = 0.f, lsq = 0.f;
#pragma unroll
            for (int j = 0; j < 32; j++) { lsum += o[j]; lsq += o[j]*o[j]; }
            lsum += __shfl_xor_sync(0xffffffffu, lsum, 8);
            lsq  += __shfl_xor_sync(0xffffffffu, lsq,  8);
            lsum += __shfl_xor_sync(0xffffffffu, lsum, 16);
            lsq  += __shfl_xor_sync(0xffffffffu, lsq,  16);
            float mean = lsum * (1.f/HID);
            float var  = lsq  * (1.f/HID) - mean*mean;
            float rstd = rsqrtf(var + 1e-5f);
#pragma unroll
            for (int j = 0; j < 32; j++)
                o[j] = (o[j] - mean)*rstd*bias[B_LNG + 128*l + ch + j]
                       + bias[B_LNB + 128*l + ch + j];
#pragma unroll
            for (int j = 0; j < 8; j++)
                *(float4*)(hr + 4*j) = make_float4(o[4*j], o[4*j+1], o[4*j+2], o[4*j+3]);
        }
        __syncthreads();
    }

    {   // pooling into qg scratch
        int cA = wsub*64 + lane, cB = cA + 32;
        float sA = 0.f, sB = 0.f, mA = -3.4e38f, mB = -3.4e38f;
#pragma unroll
        for (int nn = 0; nn < 16; nn++) {
            float a = hg[nn*HPAD + cA]; sA += a; mA = fmaxf(mA, a);
            float b = hg[nn*HPAD + cB]; sB += b; mB = fmaxf(mB, b);
        }
        qg[cA] = sA*(1.f/16.f); qg[HID + cA] = mA;
        qg[cB] = sB*(1.f/16.f); qg[HID + cB] = mB;
    }
    __syncthreads();

    // ---- MLP layer 1: two 128-row fp32 chunks of W1 ----
    {
        int cA = wsub*64 + lane, cB = cA + 32;
        float a1 = bias[B_B1 + cA];
        float a2 = bias[B_B1 + cB];
        const float* Wb = sm;          // OFF_BT = 0
        mbw(smb + MB0, 1);             // W1 rows 0..127 (arrival 7)
#pragma unroll 8
        for (int k = 0; k < 128; k++) {
            float pv = qg[k];
            a1 = fmaf(pv, Wb[k*HID + cA], a1);
            a2 = fmaf(pv, Wb[k*HID + cB], a2);
        }
        __syncthreads();
        if (tid == 0) bulk_issue(smb, W1 + 16384, 65536u, smb + MB0);
        mbw(smb + MB0, 0);             // W1 rows 128..255 (arrival 8)
#pragma unroll 8
        for (int k = 0; k < 128; k++) {
            float pv = qg[HID + k];
            a1 = fmaf(pv, Wb[k*HID + cA], a1);
            a2 = fmaf(pv, Wb[k*HID + cB], a2);
        }
        kg[cA] = fmaxf(a1, 0.f);
        kg[cB] = fmaxf(a2, 0.f);
        __syncthreads();
        if (tid == 0) bulk_issue(smb, W2, 5120u, smb + MB0);
    }
    mbw(smb + MB0, 1);                 // W2 (arrival 9)
    {
        const float* Wc = sm;
        if (wsub == 0 && lane < NC) {
            float a = bias[B_B2 + lane];
#pragma unroll 8
            for (int k = 0; k < HID; k++)
                a = fmaf(kg[k], Wc[k*NC + lane], a);
            out[((size_t)blockIdx.x*G + gs)*NC + lane] = a;
        }
    }
}

extern "C" void kernel_launch(void* const* d_in, const int* in_sizes, int n_in,
                              void* d_out, int out_size)
{
    const float* x     = (const float*)d_in[0];
    const float* enc_W = (const float*)d_in[1];
    const float* enc_b = (const float*)d_in[2];
    const float* Wq    = (const float*)d_in[3];
    const float* bq    = (const float*)d_in[4];
    const float* Wk    = (const float*)d_in[5];
    const float* bk    = (const float*)d_in[6];
    const float* Wv    = (const float*)d_in[7];
    const float* bv    = (const float*)d_in[8];
    const float* ln_g  = (const float*)d_in[9];
    const float* ln_b  = (const float*)d_in[10];
    const float* W1    = (const float*)d_in[11];
    const float* b1    = (const float*)d_in[12];
    const float* W2    = (const float*)d_in[13];
    const float* b2    = (const float*)d_in[14];
    float* out = (float*)d_out;

    prep_kernel<<<7, 256>>>(enc_W, Wq, Wk, Wv);
    cudaFuncSetAttribute(gnn_mma_kernel,
                         cudaFuncAttributeMaxDynamicSharedMemorySize, SMEM_BYTES);
    gnn_mma_kernel<<<B_TOTAL / G, THREADS, SMEM_BYTES>>>(
        x, enc_b, bq, bk, bv, ln_g, ln_b, W1, b1, W2, b2, out);
}

// round 10
// speedup vs baseline: 1.7820x; 1.0536x over previous
#include <cuda_runtime.h>
#include <cuda_bf16.h>

#define B_TOTAL 32768
#define HID 128
#define NC  10
#define G   4
#define THREADS 256
#define QP  148                  // q/k/v row stride (floats); head h at 36h
#define GFLN 7104                // per-graph floats: q|k|v, 3*16*148

// byte layout
#define AB   69632u              // A-mirror base (bytes); B tiles in [0,69632)
#define ALO  17408u              // A lo offset within mirror
#define BLO  34816u              // B lo offset within B region
#define MB0  110848u
#define MB1  110856u
#define BIAS_F 26112             // float index of bias block
#define DATA_F 27720             // float index of per-graph data
#define SMEM_BYTES 224544

#define  B_ENC 0
#define  B_BQ  128
#define  B_BK  384
#define  B_BV  640
#define  B_LNG 896
#define  B_LNB 1152
#define  B_B1  1408
#define  B_B2  1536

#define BROW 136                 // bf16 per padded B/A row (272 B)
#define BVER 34816               // bytes per B version
#define BPROJ 69632
#define W1T_OFF 487424           // 7*BPROJ
#define W1T_CH  67584            // 128 rows * 132 floats * 4

__device__ __align__(16) unsigned char g_wpre[622592];

static __device__ __forceinline__ unsigned su32(const void* p) {
    return (unsigned)__cvta_generic_to_shared(p);
}
static __device__ __forceinline__ void mbar_init(unsigned a, unsigned c) {
    asm volatile("mbarrier.init.shared.b64 [%0], %1;" :: "r"(a), "r"(c) : "memory");
}
static __device__ __forceinline__ void mbw(unsigned a, unsigned par) {
    asm volatile("{\n\t.reg .pred P;\nW%=:\n\t"
        "mbarrier.try_wait.parity.acquire.cta.shared::cta.b64 P, [%0], %1, 0x989680;\n\t"
        "@!P bra W%=;\n\t}" :: "r"(a), "r"(par) : "memory");
}
static __device__ __forceinline__ void bulk_issue(unsigned dst, const void* src,
                                                  unsigned bytes, unsigned mbar) {
    asm volatile("mbarrier.arrive.expect_tx.shared::cta.b64 _, [%0], %1;"
                 :: "r"(mbar), "r"(bytes) : "memory");
    asm volatile("cp.async.bulk.shared::cluster.global.mbarrier::complete_tx::bytes "
                 "[%0], [%1], %2, [%3];" :: "r"(dst), "l"(src), "r"(bytes), "r"(mbar)
                 : "memory");
}

#define LDSM4(r0,r1,r2,r3,adr) asm volatile( \
    "ldmatrix.sync.aligned.m8n8.x4.shared.b16 {%0,%1,%2,%3}, [%4];" \
    : "=r"(r0), "=r"(r1), "=r"(r2), "=r"(r3) : "r"(adr))

#define MMA4(acp,a,b0,b1) asm volatile( \
    "mma.sync.aligned.m16n8k16.row.col.f32.bf16.bf16.f32 " \
    "{%0,%1,%2,%3}, {%4,%5,%6,%7}, {%8,%9}, {%0,%1,%2,%3};" \
    : "+f"((acp)[0]), "+f"((acp)[1]), "+f"((acp)[2]), "+f"((acp)[3]) \
    : "r"((a)[0]), "r"((a)[1]), "r"((a)[2]), "r"((a)[3]), "r"(b0), "r"(b1))

static __device__ __forceinline__ void split2(float2 f, unsigned& hi, unsigned& lo) {
    asm("cvt.rn.bf16x2.f32 %0, %1, %2;" : "=r"(hi) : "f"(f.y), "f"(f.x));
    float lx = f.x - __uint_as_float(hi << 16);
    float ly = f.y - __uint_as_float(hi & 0xffff0000u);
    asm("cvt.rn.bf16x2.f32 %0, %1, %2;" : "=r"(lo) : "f"(ly), "f"(lx));
}
static __device__ __forceinline__ float blo(unsigned v) { return __uint_as_float(v << 16); }
static __device__ __forceinline__ float bhi(unsigned v) { return __uint_as_float(v & 0xffff0000u); }

// ---------- prep: bf16 hi/lo transposed B tiles + transposed fp32 W1 ----------
__global__ void prep_kernel(const float* __restrict__ encW, const float* __restrict__ Wq,
                            const float* __restrict__ Wk,  const float* __restrict__ Wv,
                            const float* __restrict__ W1)
{
    int b = blockIdx.x;
    if (b < 7) {
        const float* src; int K;
        if (b == 0) { src = encW; K = 64; }
        else {
            int i = b - 1, l = i / 3, w = i % 3;
            src = (w == 0 ? Wq : w == 1 ? Wk : Wv) + l*16384; K = 128;
        }
        unsigned char* dhi = g_wpre + b*BPROJ;
        for (int idx = threadIdx.x; idx < 128*BROW; idx += blockDim.x) {
            int n = idx / BROW, kk = idx % BROW;
            float v = (kk < K) ? src[kk*128 + n] : 0.f;
            __nv_bfloat16 h = __float2bfloat16(v);
            __nv_bfloat16 lo = __float2bfloat16(v - __bfloat162float(h));
            *(__nv_bfloat16*)(dhi + n*(BROW*2) + kk*2)        = h;
            *(__nv_bfloat16*)(dhi + BVER + n*(BROW*2) + kk*2) = lo;
        }
    } else {
        int chunk = b - 7;                       // W1 chunks: k<128 (mean), k>=128 (max)
        const float* src = W1 + chunk*128*128;
        float* dst = (float*)(g_wpre + W1T_OFF + chunk*W1T_CH);
        for (int idx = threadIdx.x; idx < 128*132; idx += blockDim.x) {
            int c = idx / 132, kk = idx % 132;
            dst[c*132 + kk] = (kk < 128) ? src[kk*128 + c] : 0.f;
        }
    }
}

// MMA for one projection: 2 graphs x 32 cols per warp, 3-pass bf16 split
template<int KSTEPS>
static __device__ __forceinline__ void mma_proj2(unsigned aBase0, unsigned aBase1,
                                                 unsigned bBase, float* __restrict__ acc,
                                                 int lane)
{
    const unsigned aLane = (unsigned)((lane & 15)*272 + (lane >> 4)*16);
    const int m = lane >> 3, r = lane & 7;
    const unsigned bLane = (unsigned)(((m >> 1)*8 + r)*272 + (m & 1)*16);
#pragma unroll
    for (int ks = 0; ks < KSTEPS; ks++) {
        unsigned a0h[4], a0l[4], a1h[4], a1l[4];
        unsigned aa0 = aBase0 + ks*32 + aLane;
        unsigned aa1 = aBase1 + ks*32 + aLane;
        LDSM4(a0h[0],a0h[1],a0h[2],a0h[3], aa0);
        LDSM4(a0l[0],a0l[1],a0l[2],a0l[3], aa0 + ALO);
        LDSM4(a1h[0],a1h[1],a1h[2],a1h[3], aa1);
        LDSM4(a1l[0],a1l[1],a1l[2],a1l[3], aa1 + ALO);
#pragma unroll
        for (int j = 0; j < 2; j++) {
            unsigned ab = bBase + (unsigned)(j*4352 + ks*32) + bLane;
            unsigned bh0,bh1,bh2,bh3, bl0,bl1,bl2,bl3;
            LDSM4(bh0,bh1,bh2,bh3, ab);
            LDSM4(bl0,bl1,bl2,bl3, ab + BLO);
            float* p00 = acc + j*8;
            float* p01 = acc + j*8 + 4;
            float* p10 = acc + 16 + j*8;
            float* p11 = acc + 16 + j*8 + 4;
            MMA4(p00, a0h, bh0, bh1); MMA4(p01, a0h, bh2, bh3);
            MMA4(p10, a1h, bh0, bh1); MMA4(p11, a1h, bh2, bh3);
            MMA4(p00, a0l, bh0, bh1); MMA4(p01, a0l, bh2, bh3);
            MMA4(p10, a1l, bh0, bh1); MMA4(p11, a1l, bh2, bh3);
            MMA4(p00, a0h, bl0, bl1); MMA4(p01, a0h, bl2, bl3);
            MMA4(p10, a1h, bl0, bl1); MMA4(p11, a1h, bl2, bl3);
        }
    }
}

static __device__ __forceinline__ void acc_init2(float* acc, const float* __restrict__ bp,
                                                 int cq, int lane) {
    const int q2 = (lane & 3)*2;
#pragma unroll
    for (int nt = 0; nt < 4; nt++) {
        int col = 32*cq + nt*8 + q2;
        float b0 = bp[col], b1 = bp[col + 1];
        acc[nt*4] = b0; acc[nt*4+1] = b1; acc[nt*4+2] = b0; acc[nt*4+3] = b1;
        acc[16 + nt*4] = b0; acc[16 + nt*4+1] = b1;
        acc[16 + nt*4+2] = b0; acc[16 + nt*4+3] = b1;
    }
}

__global__ void __launch_bounds__(THREADS, 1)
gnn_mma_kernel(const float* __restrict__ x,
               const float* __restrict__ enc_b, const float* __restrict__ bq,
               const float* __restrict__ bk,    const float* __restrict__ bv,
               const float* __restrict__ ln_g,  const float* __restrict__ ln_b,
               const float* __restrict__ W1,    const float* __restrict__ b1,
               const float* __restrict__ W2,    const float* __restrict__ b2,
               float* __restrict__ out)
{
    extern __shared__ float sm[];
    char* smc = (char*)sm;
    const unsigned smb = su32(sm);
    float* bias  = sm + BIAS_F;
    float* dataF = sm + DATA_F;
    const int tid = threadIdx.x, lane = tid & 31, warp = tid >> 5;
    const int gs = warp >> 1, wsub = warp & 1, n0 = wsub * 8;
    const int gp = warp >> 2, cq = warp & 3;       // MMA mapping
    const int gq = lane >> 2, q2 = (lane & 3)*2;

    if (tid == 0) {
        mbar_init(smb + MB0, 1); mbar_init(smb + MB1, 1);
        asm volatile("fence.proxy.async.shared::cta;" ::: "memory");
        bulk_issue(smb,       g_wpre,        BVER, smb + MB0);     // enc hi
        bulk_issue(smb + BLO, g_wpre + BVER, BVER, smb + MB1);     // enc lo
    }
    for (int i = tid; i < 128; i += THREADS) { bias[B_ENC+i] = enc_b[i]; bias[B_B1+i] = b1[i]; }
    for (int i = tid; i < 256; i += THREADS) {
        bias[B_BQ+i] = bq[i]; bias[B_BK+i] = bk[i]; bias[B_BV+i] = bv[i];
        bias[B_LNG+i] = ln_g[i]; bias[B_LNB+i] = ln_b[i];
    }
    if (tid < NC) bias[B_B2 + tid] = b2[tid];
    {   // stage x directly as bf16 hi/lo A-mirror (K = 64)
        const float4* xs = (const float4*)(x + (size_t)blockIdx.x * (G*16*64));
        for (int i = tid; i < 1024; i += THREADS) {
            int g = i >> 8, row = (i >> 4) & 15, kq = i & 15;
            float4 t = xs[i];
            unsigned h0,l0,h1,l1;
            split2(make_float2(t.x, t.y), h0, l0);
            split2(make_float2(t.z, t.w), h1, l1);
            unsigned off = AB + (unsigned)((g*16 + row)*272 + kq*8);
            *(unsigned*)(smc + off)           = h0;
            *(unsigned*)(smc + off + 4)       = h1;
            *(unsigned*)(smc + off + ALO)     = l0;
            *(unsigned*)(smc + off + ALO + 4) = l1;
        }
    }
    __syncthreads();

    const unsigned aB0 = smb + AB + (unsigned)((2*gp    )*16*272);
    const unsigned aB1 = smb + AB + (unsigned)((2*gp + 1)*16*272);
    const unsigned bB  = smb + (unsigned)(cq*8704);
    float acc[32];

    // ---- encode: h = x @ enc_W + enc_b  -> A-mirror only ----
    mbw(smb + MB0, 0); mbw(smb + MB1, 0);
    acc_init2(acc, bias + B_ENC, cq, lane);
    mma_proj2<4>(aB0, aB1, bB, acc, lane);
    __syncthreads();
    if (tid == 0) {
        bulk_issue(smb,       g_wpre + BPROJ,        BVER, smb + MB0);
        bulk_issue(smb + BLO, g_wpre + BPROJ + BVER, BVER, smb + MB1);
    }
#pragma unroll
    for (int ga = 0; ga < 2; ga++) {
        int g = 2*gp + ga;
#pragma unroll
        for (int nt = 0; nt < 4; nt++) {
            int idx = ga*16 + nt*4;
            int lc  = 32*cq + nt*8 + q2;
            unsigned h0,l0,h1,l1;
            split2(make_float2(acc[idx],   acc[idx+1]), h0, l0);
            split2(make_float2(acc[idx+2], acc[idx+3]), h1, l1);
            unsigned o0 = AB + (unsigned)((g*16 + gq)*272 + lc*2);
            *(unsigned*)(smc + o0)       = h0;
            *(unsigned*)(smc + o0 + ALO) = l0;
            unsigned o1 = o0 + 8*272;
            *(unsigned*)(smc + o1)       = h1;
            *(unsigned*)(smc + o1 + ALO) = l1;
        }
    }
    __syncthreads();

    const float scale = 0.1767766952966369f;
    for (int l = 0; l < 2; l++) {
        for (int s = 0; s < 3; s++) {
            int pidx = 1 + l*3 + s;
            mbw(smb + MB0, pidx & 1); mbw(smb + MB1, pidx & 1);
            const float* bp = bias + (s == 0 ? B_BQ : s == 1 ? B_BK : B_BV) + 128*l;
            acc_init2(acc, bp, cq, lane);
            mma_proj2<8>(aB0, aB1, bB, acc, lane);
            __syncthreads();
            if (tid == 0) {
                int np = pidx + 1;
                if (np <= 6) {
                    bulk_issue(smb,       g_wpre + np*BPROJ,        BVER, smb + MB0);
                    bulk_issue(smb + BLO, g_wpre + np*BPROJ + BVER, BVER, smb + MB1);
                } else {
                    bulk_issue(smb, g_wpre + W1T_OFF, W1T_CH, smb + MB0);
                }
            }
            // epilogue: q/k/v fp32, head-padded rows
#pragma unroll
            for (int ga = 0; ga < 2; ga++) {
                float* base = dataF + (2*gp + ga)*GFLN + s*2368;
#pragma unroll
                for (int nt = 0; nt < 4; nt++) {
                    int idx = ga*16 + nt*4;
                    int off = cq*36 + nt*8 + q2;
                    *(float2*)(base + gq*QP + off)       = make_float2(acc[idx],   acc[idx+1]);
                    *(float2*)(base + (gq + 8)*QP + off) = make_float2(acc[idx+2], acc[idx+3]);
                }
            }
        }
        __syncthreads();

        // ---- attention + residual(from mirror) + LN (writes new mirror) ----
        {
            float* qg = dataF + gs*GFLN;
            float* kg = qg + 2368;
            float* vg = kg + 2368;
            const int n  = n0 + (lane & 7);
            const int hh = lane >> 3;
            const int co = hh * 36, ch = hh * 32;
            float q[32];
            const float* qr = qg + n*QP + co;
#pragma unroll
            for (int j = 0; j < 8; j++) {
                float4 t = *(const float4*)(qr + 4*j);
                q[4*j] = t.x; q[4*j+1] = t.y; q[4*j+2] = t.z; q[4*j+3] = t.w;
            }
            float s[16];
#pragma unroll
            for (int m = 0; m < 16; m++) {
                const float* kr = kg + m*QP + co;
                float a0 = 0.f, a1 = 0.f, a2 = 0.f, a3 = 0.f;
#pragma unroll
                for (int j = 0; j < 8; j++) {
                    float4 t = *(const float4*)(kr + 4*j);
                    a0 += q[4*j]*t.x; a1 += q[4*j+1]*t.y;
                    a2 += q[4*j+2]*t.z; a3 += q[4*j+3]*t.w;
                }
                s[m] = (a0 + a1 + a2 + a3) * scale;
            }
            float mx = s[0];
#pragma unroll
            for (int m = 1; m < 16; m++) mx = fmaxf(mx, s[m]);
            float ssum = 0.f;
#pragma unroll
            for (int m = 0; m < 16; m++) { s[m] = __expf(s[m] - mx); ssum += s[m]; }
            float inv = 1.f / ssum;
            float o[32];
#pragma unroll
            for (int j = 0; j < 32; j++) o[j] = 0.f;
#pragma unroll
            for (int m = 0; m < 16; m++) {
                float p = s[m] * inv;
                const float* vr = vg + m*QP + co;
#pragma unroll
                for (int j = 0; j < 8; j++) {
                    float4 t = *(const float4*)(vr + 4*j);
                    o[4*j] += p*t.x; o[4*j+1] += p*t.y;
                    o[4*j+2] += p*t.z; o[4*j+3] += p*t.w;
                }
            }
            // residual from bf16 mirror (h = hi + lo)
            char* ap = smc + AB + (unsigned)((gs*16 + n)*272 + ch*2);
#pragma unroll
            for (int u = 0; u < 4; u++) {
                uint4 H = *(const uint4*)(ap + 16*u);
                uint4 L = *(const uint4*)(ap + ALO + 16*u);
                o[8*u]   += blo(H.x) + blo(L.x);  o[8*u+1] += bhi(H.x) + bhi(L.x);
                o[8*u+2] += blo(H.y) + blo(L.y);  o[8*u+3] += bhi(H.y) + bhi(L.y);
                o[8*u+4] += blo(H.z) + blo(L.z);  o[8*u+5] += bhi(H.z) + bhi(L.z);
                o[8*u+6] += blo(H.w) + blo(L.w);  o[8*u+7] += bhi(H.w) + bhi(L.w);
            }
            float lsum = 0.f, lsq = 0.f;
#pragma unroll
            for (int j = 0; j < 32; j++) { lsum += o[j]; lsq += o[j]*o[j]; }
            lsum += __shfl_xor_sync(0xffffffffu, lsum, 8);
            lsq  += __shfl_xor_sync(0xffffffffu, lsq,  8);
            lsum += __shfl_xor_sync(0xffffffffu, lsum, 16);
            lsq  += __shfl_xor_sync(0xffffffffu, lsq,  16);
            float mean = lsum * (1.f/HID);
            float var  = lsq  * (1.f/HID) - mean*mean;
            float rstd = rsqrtf(var + 1e-5f);
#pragma unroll
            for (int j = 0; j < 32; j++)
                o[j] = (o[j] - mean)*rstd*bias[B_LNG + 128*l + ch + j]
                       + bias[B_LNB + 128*l + ch + j];
            // write new h mirror
#pragma unroll
            for (int u = 0; u < 4; u++) {
                unsigned hh4[4], ll4[4];
#pragma unroll
                for (int e = 0; e < 4; e++)
                    split2(make_float2(o[8*u + 2*e], o[8*u + 2*e + 1]), hh4[e], ll4[e]);
                *(uint4*)(ap + 16*u)       = make_uint4(hh4[0], hh4[1], hh4[2], hh4[3]);
                *(uint4*)(ap + ALO + 16*u) = make_uint4(ll4[0], ll4[1], ll4[2], ll4[3]);
            }
        }
        __syncthreads();
    }

    {   // pooling from mirror -> fp32 scratch (mean | max), staggered per graph
        int cp = wsub*64 + 2*lane;
        const char* ap = smc + AB + (unsigned)((gs*16)*272 + cp*2);
        float s0 = 0.f, s1 = 0.f, m0 = -3.4e38f, m1 = -3.4e38f;
#pragma unroll
        for (int nn = 0; nn < 16; nn++) {
            unsigned H = *(const unsigned*)(ap + nn*272);
            unsigned L = *(const unsigned*)(ap + nn*272 + ALO);
            float h0 = blo(H) + blo(L), h1 = bhi(H) + bhi(L);
            s0 += h0; m0 = fmaxf(m0, h0);
            s1 += h1; m1 = fmaxf(m1, h1);
        }
        float* scr = dataF + gs*GFLN + 8*gs;
        *(float2*)(scr + cp)       = make_float2(s0*(1.f/16.f), s1*(1.f/16.f));
        *(float2*)(scr + 128 + cp) = make_float2(m0, m1);
    }
    __syncthreads();

    // ---- MLP layer 1: transposed fp32 W1 (two k-chunks), warp = 16 cols x 4 graphs ----
    {
        int g2 = lane >> 3, c8 = lane & 7;
        int c = warp*16 + c8;
        float a1 = bias[B_B1 + c], a2 = bias[B_B1 + c + 8];
        const float* pooled = dataF + g2*GFLN + 8*g2;
        const float* Wb = sm;
        mbw(smb + MB0, 1);                     // W1T chunk0 (8th arrival)
#pragma unroll 4
        for (int k4 = 0; k4 < 32; k4++) {
            float4 p = *(const float4*)(pooled + 4*k4);
            float4 w = *(const float4*)(Wb + c*132 + 4*k4);
            float4 v = *(const float4*)(Wb + (c + 8)*132 + 4*k4);
            a1 = fmaf(p.x, w.x, fmaf(p.y, w.y, fmaf(p.z, w.z, fmaf(p.w, w.w, a1))));
            a2 = fmaf(p.x, v.x, fmaf(p.y, v.y, fmaf(p.z, v.z, fmaf(p.w, v.w, a2))));
        }
        __syncthreads();
        if (tid == 0) bulk_issue(smb, g_wpre + W1T_OFF + W1T_CH, W1T_CH, smb + MB0);
        mbw(smb + MB0, 0);                     // chunk1 (9th arrival)
#pragma unroll 4
        for (int k4 = 0; k4 < 32; k4++) {
            float4 p = *(const float4*)(pooled + 128 + 4*k4);
            float4 w = *(const float4*)(Wb + c*132 + 4*k4);
            float4 v = *(const float4*)(Wb + (c + 8)*132 + 4*k4);
            a1 = fmaf(p.x, w.x, fmaf(p.y, w.y, fmaf(p.z, w.z, fmaf(p.w, w.w, a1))));
            a2 = fmaf(p.x, v.x, fmaf(p.y, v.y, fmaf(p.z, v.z, fmaf(p.w, v.w, a2))));
        }
        float* hid = dataF + g2*GFLN + 512 + 8*g2;
        hid[c]     = fmaxf(a1, 0.f);
        hid[c + 8] = fmaxf(a2, 0.f);
        __syncthreads();
        if (tid == 0) bulk_issue(smb, W2, 5120u, smb + MB0);
    }
    mbw(smb + MB0, 1);                         // W2 (10th arrival)
    {
        const float* Wc = sm;
        if (wsub == 0 && lane < NC) {
            const float* hid = dataF + gs*GFLN + 512 + 8*gs;
            float a = bias[B_B2 + lane];
#pragma unroll 8
            for (int k = 0; k < HID; k++)
                a = fmaf(hid[k], Wc[k*NC + lane], a);
            out[((size_t)blockIdx.x*G + gs)*NC + lane] = a;
        }
    }
}

extern "C" void kernel_launch(void* const* d_in, const int* in_sizes, int n_in,
                              void* d_out, int out_size)
{
    const float* x     = (const float*)d_in[0];
    const float* enc_W = (const float*)d_in[1];
    const float* enc_b = (const float*)d_in[2];
    const float* Wq    = (const float*)d_in[3];
    const float* bq    = (const float*)d_in[4];
    const float* Wk    = (const float*)d_in[5];
    const float* bk    = (const float*)d_in[6];
    const float* Wv    = (const float*)d_in[7];
    const float* bv    = (const float*)d_in[8];
    const float* ln_g  = (const float*)d_in[9];
    const float* ln_b  = (const float*)d_in[10];
    const float* W1    = (const float*)d_in[11];
    const float* b1    = (const float*)d_in[12];
    const float* W2    = (const float*)d_in[13];
    const float* b2    = (const float*)d_in[14];
    float* out = (float*)d_out;

    prep_kernel<<<9, 256>>>(enc_W, Wq, Wk, Wv, W1);
    cudaFuncSetAttribute(gnn_mma_kernel,
                         cudaFuncAttributeMaxDynamicSharedMemorySize, SMEM_BYTES);
    gnn_mma_kernel<<<B_TOTAL / G, THREADS, SMEM_BYTES>>>(
        x, enc_b, bq, bk, bv, ln_g, ln_b, W1, b1, W2, b2, out);
}